// round 3
// baseline (speedup 1.0000x reference)
#include <cuda_runtime.h>
#include <math.h>

#define GN 50000          // nodes
#define GH 128            // hidden dim
#define EMAX 800000       // edges

// ---------------- device scratch (no allocations allowed) ----------------
__device__ float g_m  [GN * GH];   // message linear output
__device__ float g_pre[GN * GH];   // x@Wu^T + bu
__device__ float g_h  [GN * GH];   // layer activations
__device__ float g_W  [GH * 256];  // packed [k][j]: j<128 -> Wm^T, j>=128 -> Wu^T
__device__ int   g_rowptr[GN + 1];
__device__ int   g_cursor[GN];
__device__ int   g_src[EMAX];
__device__ float g_wt [EMAX];
__device__ int   g_is64;           // 1 if edge_index buffer is int64, else int32

// ---------------- dtype detection ----------------
// Safe region under BOTH interpretations: first 2E int32 words.
// int64 layout (little-endian, values in [0,50000)): words alternate [val, 0].
__global__ void detect_init_kernel() { g_is64 = 1; }

__global__ void detect_kernel(const int* __restrict__ w, int E) {
    int e = blockIdx.x * blockDim.x + threadIdx.x;
    if (e < E) {
        int lo = w[2 * e];
        int hi = w[2 * e + 1];
        if (hi != 0 || lo < 0 || lo >= GN) g_is64 = 0;
    }
}

// ---------------- CSR build ----------------
__global__ void zero_rowptr_kernel() {
    int i = blockIdx.x * blockDim.x + threadIdx.x;
    if (i <= GN) g_rowptr[i] = 0;
}

__global__ void count_kernel(const int* __restrict__ w, int E) {
    int e = blockIdx.x * blockDim.x + threadIdx.x;
    if (e < E) {
        int d = g_is64 ? w[2 * E + 2 * e] : w[E + e];
        if ((unsigned)d < (unsigned)GN) atomicAdd(&g_rowptr[d + 1], 1);
    }
}

// single-block inclusive scan over rowptr[0..GN]; also initializes cursor
__global__ void scan_kernel() {
    __shared__ int wsum[32];
    int tid  = threadIdx.x;
    int lane = tid & 31;
    int wid  = tid >> 5;
    int carry = 0;
    for (int base = 0; base < GN + 1; base += 1024) {
        int i = base + tid;
        int v = (i < GN + 1) ? g_rowptr[i] : 0;
        #pragma unroll
        for (int o = 1; o < 32; o <<= 1) {
            int n = __shfl_up_sync(0xffffffffu, v, o);
            if (lane >= o) v += n;
        }
        if (lane == 31) wsum[wid] = v;
        __syncthreads();
        if (wid == 0) {
            int s = wsum[lane];
            #pragma unroll
            for (int o = 1; o < 32; o <<= 1) {
                int n = __shfl_up_sync(0xffffffffu, s, o);
                if (lane >= o) s += n;
            }
            wsum[lane] = s;
        }
        __syncthreads();
        int add = carry + (wid ? wsum[wid - 1] : 0);
        v += add;
        if (i < GN + 1) g_rowptr[i] = v;
        if (i < GN)     g_cursor[i] = v;
        carry += wsum[31];
        __syncthreads();
    }
}

__global__ void fill_kernel(const int* __restrict__ w,
                            const float* __restrict__ ew, int E) {
    int e = blockIdx.x * blockDim.x + threadIdx.x;
    if (e < E) {
        int s, d;
        if (g_is64) { s = w[2 * e]; d = w[2 * E + 2 * e]; }
        else        { s = w[e];     d = w[E + e]; }
        if ((unsigned)s < (unsigned)GN && (unsigned)d < (unsigned)GN) {
            int p = atomicAdd(&g_cursor[d], 1);
            g_src[p] = s;
            g_wt[p]  = ew[e];
        }
    }
}

// ---------------- pack weights: g_W[k*256 + j] ----------------
__global__ void pack_w_kernel(const float* __restrict__ Wm,
                              const float* __restrict__ Wu) {
    int idx = blockIdx.x * blockDim.x + threadIdx.x;   // 128*256
    if (idx < GH * 256) {
        int k = idx >> 8;
        int j = idx & 255;
        g_W[idx] = (j < 128) ? Wm[j * GH + k] : Wu[(j - 128) * GH + k];
    }
}

// ---------------- fused dual GEMM: C = A @ g_W
// blockIdx.y==0 -> g_m (cols 0..127);  ==1 -> g_pre + bu (cols 128..255)
// Tile 64 rows x 128 cols, TK=16, 256 threads, thread tile 8x4, scalar FFMA.
__global__ void __launch_bounds__(256) gemm_dual_kernel(
        const float* __restrict__ Aext, int use_gh, const float* __restrict__ bu) {
    __shared__ float As[16][64];
    __shared__ float Bs[16][128];
    const float* A = use_gh ? g_h : Aext;
    int t     = threadIdx.x;
    int trow  = t >> 5;        // 0..7
    int tcol  = t & 31;        // 0..31
    int row0  = blockIdx.x * 64;
    int ntile = blockIdx.y;

    float acc[8][4];
    #pragma unroll
    for (int i = 0; i < 8; i++)
        #pragma unroll
        for (int j = 0; j < 4; j++) acc[i][j] = 0.f;

    for (int k0 = 0; k0 < GH; k0 += 16) {
        {   // A tile 64x16 -> As[k][m]
            int idx = t * 4;
            int ar  = idx >> 4;
            int ak  = idx & 15;
            float4 av = make_float4(0.f, 0.f, 0.f, 0.f);
            int grow = row0 + ar;
            if (grow < GN) av = *(const float4*)&A[(size_t)grow * GH + k0 + ak];
            As[ak + 0][ar] = av.x;
            As[ak + 1][ar] = av.y;
            As[ak + 2][ar] = av.z;
            As[ak + 3][ar] = av.w;
        }
        {   // B tile 16x128
            int bidx = t * 8;
            int bk   = bidx >> 7;
            int bj   = bidx & 127;
            const float* gp = &g_W[(k0 + bk) * 256 + ntile * 128 + bj];
            *(float4*)&Bs[bk][bj]     = *(const float4*)gp;
            *(float4*)&Bs[bk][bj + 4] = *(const float4*)(gp + 4);
        }
        __syncthreads();
        #pragma unroll
        for (int kk = 0; kk < 16; kk++) {
            float a[8];
            #pragma unroll
            for (int i = 0; i < 8; i++) a[i] = As[kk][trow * 8 + i];
            float4 bv = *(const float4*)&Bs[kk][tcol * 4];
            #pragma unroll
            for (int i = 0; i < 8; i++) {
                acc[i][0] = fmaf(a[i], bv.x, acc[i][0]);
                acc[i][1] = fmaf(a[i], bv.y, acc[i][1]);
                acc[i][2] = fmaf(a[i], bv.z, acc[i][2]);
                acc[i][3] = fmaf(a[i], bv.w, acc[i][3]);
            }
        }
        __syncthreads();
    }

    int colb = tcol * 4;
    if (ntile == 0) {
        #pragma unroll
        for (int i = 0; i < 8; i++) {
            int r = row0 + trow * 8 + i;
            if (r < GN) {
                float4 v = make_float4(acc[i][0], acc[i][1], acc[i][2], acc[i][3]);
                *(float4*)&g_m[(size_t)r * GH + colb] = v;
            }
        }
    } else {
        float4 b4 = *(const float4*)&bu[colb];
        #pragma unroll
        for (int i = 0; i < 8; i++) {
            int r = row0 + trow * 8 + i;
            if (r < GN) {
                float4 v = make_float4(acc[i][0] + b4.x, acc[i][1] + b4.y,
                                       acc[i][2] + b4.z, acc[i][3] + b4.w);
                *(float4*)&g_pre[(size_t)r * GH + colb] = v;
            }
        }
    }
}

// ---------------- aggregate + tanh: one warp per destination node ----------------
__global__ void __launch_bounds__(256) aggregate_kernel() {
    int warp = (blockIdx.x * blockDim.x + threadIdx.x) >> 5;
    int lane = threadIdx.x & 31;
    if (warp >= GN) return;
    int beg = g_rowptr[warp];
    int end = g_rowptr[warp + 1];
    float4 acc  = *(const float4*)&g_pre[(size_t)warp * GH + lane * 4];
    float4 acc2 = make_float4(0.f, 0.f, 0.f, 0.f);
    int p = beg;
    for (; p + 1 < end; p += 2) {
        int s0 = g_src[p];     float w0 = g_wt[p];
        int s1 = g_src[p + 1]; float w1 = g_wt[p + 1];
        float4 m0 = *(const float4*)&g_m[(size_t)s0 * GH + lane * 4];
        float4 m1 = *(const float4*)&g_m[(size_t)s1 * GH + lane * 4];
        acc.x  = fmaf(w0, m0.x, acc.x);  acc.y  = fmaf(w0, m0.y, acc.y);
        acc.z  = fmaf(w0, m0.z, acc.z);  acc.w  = fmaf(w0, m0.w, acc.w);
        acc2.x = fmaf(w1, m1.x, acc2.x); acc2.y = fmaf(w1, m1.y, acc2.y);
        acc2.z = fmaf(w1, m1.z, acc2.z); acc2.w = fmaf(w1, m1.w, acc2.w);
    }
    if (p < end) {
        int s = g_src[p]; float w = g_wt[p];
        float4 mv = *(const float4*)&g_m[(size_t)s * GH + lane * 4];
        acc.x = fmaf(w, mv.x, acc.x); acc.y = fmaf(w, mv.y, acc.y);
        acc.z = fmaf(w, mv.z, acc.z); acc.w = fmaf(w, mv.w, acc.w);
    }
    acc.x += acc2.x; acc.y += acc2.y; acc.z += acc2.z; acc.w += acc2.w;
    float4 r;
    r.x = tanhf(acc.x); r.y = tanhf(acc.y); r.z = tanhf(acc.z); r.w = tanhf(acc.w);
    *(float4*)&g_h[(size_t)warp * GH + lane * 4] = r;
}

// ---------------- output projection: out = h @ Wout^T + bout ----------------
__global__ void __launch_bounds__(256) out_gemm_kernel(
        const float* __restrict__ Wout, const float* __restrict__ bout,
        float* __restrict__ out) {
    __shared__ float Ws[128][32];   // Ws[k][c] = Wout[c*128+k]
    __shared__ float Hs[8][128];
    int t = threadIdx.x;
    for (int i = t; i < 32 * 128; i += 256) {
        int c = i & 31;
        int k = i >> 5;
        Ws[k][c] = Wout[c * GH + k];
    }
    int row0 = blockIdx.x * 8;
    {
        int idx = t * 4;
        int r   = idx >> 7;
        int k   = idx & 127;
        float4 hv = make_float4(0.f, 0.f, 0.f, 0.f);
        if (row0 + r < GN) hv = *(const float4*)&g_h[(size_t)(row0 + r) * GH + k];
        *(float4*)&Hs[r][k] = hv;
    }
    __syncthreads();
    int w    = t >> 5;
    int lane = t & 31;
    int row  = row0 + w;
    float acc = bout[lane];
    #pragma unroll
    for (int k = 0; k < GH; k++) acc = fmaf(Hs[w][k], Ws[k][lane], acc);
    if (row < GN) out[row * 32 + lane] = acc;
}

// ---------------- launch ----------------
extern "C" void kernel_launch(void* const* d_in, const int* in_sizes, int n_in,
                              void* d_out, int out_size) {
    const float* x    = (const float*)d_in[0];
    const int*   ei   = (const int*)d_in[1];    // int32 words; dtype detected on device
    const float* ew   = (const float*)d_in[2];
    const float* Wm[3] = {(const float*)d_in[3], (const float*)d_in[6], (const float*)d_in[9]};
    const float* Wu[3] = {(const float*)d_in[4], (const float*)d_in[7], (const float*)d_in[10]};
    const float* bu[3] = {(const float*)d_in[5], (const float*)d_in[8], (const float*)d_in[11]};
    const float* Wout = (const float*)d_in[12];
    const float* bout = (const float*)d_in[13];
    float*       out  = (float*)d_out;

    int E = in_sizes[1] / 2;   // element count / 2 regardless of dtype

    // dtype detection + CSR build (once; identical for all 3 layers)
    detect_init_kernel<<<1, 1>>>();
    detect_kernel<<<(E + 255) / 256, 256>>>(ei, E);
    zero_rowptr_kernel<<<(GN + 256) / 256, 256>>>();
    count_kernel<<<(E + 255) / 256, 256>>>(ei, E);
    scan_kernel<<<1, 1024>>>();
    fill_kernel<<<(E + 255) / 256, 256>>>(ei, ew, E);

    dim3 ggrid((GN + 63) / 64, 2);
    int  agg_blocks = (GN * 32 + 255) / 256;

    for (int l = 0; l < 3; l++) {
        pack_w_kernel<<<(GH * 256 + 255) / 256, 256>>>(Wm[l], Wu[l]);
        gemm_dual_kernel<<<ggrid, 256>>>(x, l > 0 ? 1 : 0, bu[l]);
        aggregate_kernel<<<agg_blocks, 256>>>();
    }

    out_gemm_kernel<<<(GN + 7) / 8, 256>>>(Wout, bout, out);
}